// round 1
// baseline (speedup 1.0000x reference)
#include <cuda_runtime.h>
#include <cuda_bf16.h>
#include <stdint.h>

#define D 128
#define DV 32              // float4 chunks per row
#define MAXN 50048
#define MAXE 1600000

__device__ int   g_row[MAXE];
__device__ int   g_col[MAXE];
__device__ int   g_deg[MAXN];
__device__ float g_dis[MAXN];
__device__ float g_a[MAXN * D];   // aggregated features
__device__ float g_h[MAXN * D];   // hidden after layer 1
__device__ int   g_is64;

// ---------------------------------------------------------------------------
// Detect edge_index dtype: int64 little-endian with values < 2^32 means every
// odd 32-bit word is zero. int32 random indices in [0,50000) make that
// astronomically unlikely over 2048 samples.
// ---------------------------------------------------------------------------
__global__ void k_detect(const unsigned* p) {
    __shared__ int any_nz;
    if (threadIdx.x == 0) any_nz = 0;
    __syncthreads();
    int local = 0;
    for (int i = 1 + 2 * threadIdx.x; i < 4096; i += 2 * blockDim.x)
        if (p[i]) local = 1;
    if (local) any_nz = 1;   // benign race, all writers store 1
    __syncthreads();
    if (threadIdx.x == 0) g_is64 = any_nz ? 0 : 1;
}

__global__ void k_norm_edges(const void* p, int E) {
    int e = blockIdx.x * blockDim.x + threadIdx.x;
    if (e >= E) return;
    if (g_is64) {
        const long long* q = (const long long*)p;
        g_row[e] = (int)q[e];
        g_col[e] = (int)q[(long long)E + e];
    } else {
        const int* q = (const int*)p;
        g_row[e] = q[e];
        g_col[e] = q[E + e];
    }
}

__global__ void k_deg_init(int N) {
    int i = blockIdx.x * blockDim.x + threadIdx.x;
    if (i < N) g_deg[i] = 1;   // self loop
}

__global__ void k_deg_count(int E) {
    int e = blockIdx.x * blockDim.x + threadIdx.x;
    if (e < E) atomicAdd(&g_deg[g_row[e]], 1);
}

__global__ void k_dis(int N) {
    int i = blockIdx.x * blockDim.x + threadIdx.x;
    if (i < N) g_dis[i] = rsqrtf((float)g_deg[i]);
}

// ---------------------------------------------------------------------------
// Aggregation: dst = Agg(src).  Self-loop contribution initializes dst.
// ---------------------------------------------------------------------------
__global__ void k_self(const float4* __restrict__ src, float4* __restrict__ dst, int N) {
    int t = blockIdx.x * blockDim.x + threadIdx.x;
    if (t >= N * DV) return;
    int i = t >> 5;
    float s = g_dis[i];
    s *= s;
    float4 v = src[t];
    dst[t] = make_float4(s * v.x, s * v.y, s * v.z, s * v.w);
}

__global__ void k_edge(const float4* __restrict__ src, float4* __restrict__ dst, int E) {
    int t = blockIdx.x * blockDim.x + threadIdx.x;
    if (t >= E * DV) return;
    int e = t >> 5;
    int c = t & 31;
    int r = g_row[e];
    int d = g_col[e];
    float w = g_dis[r] * g_dis[d];
    float4 v = src[r * DV + c];
    float4* addr = dst + (d * DV + c);
    asm volatile("red.global.add.v4.f32 [%0], {%1,%2,%3,%4};"
                 :: "l"(addr), "f"(w * v.x), "f"(w * v.y), "f"(w * v.z), "f"(w * v.w)
                 : "memory");
}

// ---------------------------------------------------------------------------
// GEMM: C[N,128] = A[N,128] @ W[128,128] + bias, optional ReLU.
// BM=64, BN=128, BK=64 (two k-steps), 256 threads, 4x8 register tile.
// ---------------------------------------------------------------------------
template <bool RELU>
__global__ void k_gemm(const float* __restrict__ A, const float* __restrict__ W,
                       const float* __restrict__ bias, float* __restrict__ C, int N) {
    __shared__ float As[64][64];    // [k][m]
    __shared__ float Ws[64][128];   // [k][n]

    const int tid = threadIdx.x;
    const int tm = tid >> 4;    // 0..15 -> 4 rows each
    const int tn = tid & 15;    // 0..15 -> 8 cols each
    const int row0 = blockIdx.x * 64;

    float acc[4][8];
    #pragma unroll
    for (int i = 0; i < 4; i++)
        #pragma unroll
        for (int j = 0; j < 8; j++) acc[i][j] = 0.f;

    for (int kk = 0; kk < D; kk += 64) {
        // A tile: 64 rows x 64 k = 1024 float4, 4 per thread; store k-major.
        #pragma unroll
        for (int it = 0; it < 4; it++) {
            int idx = tid + it * 256;
            int m  = idx >> 4;       // row in tile
            int k4 = idx & 15;       // float4 index along k
            float4 v = make_float4(0.f, 0.f, 0.f, 0.f);
            int gr = row0 + m;
            if (gr < N) v = *(const float4*)(A + (long)gr * D + kk + k4 * 4);
            As[k4 * 4 + 0][m] = v.x;
            As[k4 * 4 + 1][m] = v.y;
            As[k4 * 4 + 2][m] = v.z;
            As[k4 * 4 + 3][m] = v.w;
        }
        // W tile: 64 k x 128 n = 2048 float4, 8 per thread.
        #pragma unroll
        for (int it = 0; it < 8; it++) {
            int idx = tid + it * 256;
            int k  = idx >> 5;
            int n4 = idx & 31;
            *(float4*)&Ws[k][n4 * 4] = *(const float4*)(W + (kk + k) * D + n4 * 4);
        }
        __syncthreads();

        #pragma unroll 8
        for (int k = 0; k < 64; k++) {
            float4 av = *(const float4*)&As[k][tm * 4];
            float4 b0 = *(const float4*)&Ws[k][tn * 8];
            float4 b1 = *(const float4*)&Ws[k][tn * 8 + 4];
            float a[4] = {av.x, av.y, av.z, av.w};
            float b[8] = {b0.x, b0.y, b0.z, b0.w, b1.x, b1.y, b1.z, b1.w};
            #pragma unroll
            for (int i = 0; i < 4; i++)
                #pragma unroll
                for (int j = 0; j < 8; j++)
                    acc[i][j] += a[i] * b[j];
        }
        __syncthreads();
    }

    float4 bv0 = *(const float4*)(bias + tn * 8);
    float4 bv1 = *(const float4*)(bias + tn * 8 + 4);
    #pragma unroll
    for (int i = 0; i < 4; i++) {
        int gr = row0 + tm * 4 + i;
        if (gr >= N) continue;
        float o[8];
        o[0] = acc[i][0] + bv0.x; o[1] = acc[i][1] + bv0.y;
        o[2] = acc[i][2] + bv0.z; o[3] = acc[i][3] + bv0.w;
        o[4] = acc[i][4] + bv1.x; o[5] = acc[i][5] + bv1.y;
        o[6] = acc[i][6] + bv1.z; o[7] = acc[i][7] + bv1.w;
        if (RELU) {
            #pragma unroll
            for (int j = 0; j < 8; j++) o[j] = fmaxf(o[j], 0.f);
        }
        *(float4*)(C + (long)gr * D + tn * 8)     = make_float4(o[0], o[1], o[2], o[3]);
        *(float4*)(C + (long)gr * D + tn * 8 + 4) = make_float4(o[4], o[5], o[6], o[7]);
    }
}

extern "C" void kernel_launch(void* const* d_in, const int* in_sizes, int n_in,
                              void* d_out, int out_size) {
    const float* x  = (const float*)d_in[0];
    const void*  ei = d_in[1];
    const float* W1 = (const float*)d_in[2];
    const float* b1 = (const float*)d_in[3];
    const float* W2 = (const float*)d_in[4];
    const float* b2 = (const float*)d_in[5];
    float* out = (float*)d_out;

    const int N = in_sizes[0] / D;
    const int E = in_sizes[1] / 2;

    float* a_ptr = nullptr;
    float* h_ptr = nullptr;
    cudaGetSymbolAddress((void**)&a_ptr, g_a);
    cudaGetSymbolAddress((void**)&h_ptr, g_h);

    const int T = 256;
    // ---- prep: dtype normalize, degrees, norms ----
    k_detect<<<1, 256>>>((const unsigned*)ei);
    k_norm_edges<<<(E + T - 1) / T, T>>>(ei, E);
    k_deg_init<<<(N + T - 1) / T, T>>>(N);
    k_deg_count<<<(E + T - 1) / T, T>>>(E);
    k_dis<<<(N + T - 1) / T, T>>>(N);

    const int selfGrid = (N * DV + T - 1) / T;
    const int edgeGrid = (E * DV + T - 1) / T;
    const int gemmGrid = (N + 63) / 64;

    // ---- layer 1: a = Agg(x); h = relu(a @ W1 + b1) ----
    k_self<<<selfGrid, T>>>((const float4*)x, (float4*)a_ptr, N);
    k_edge<<<edgeGrid, T>>>((const float4*)x, (float4*)a_ptr, E);
    k_gemm<true><<<gemmGrid, T>>>(a_ptr, W1, b1, h_ptr, N);

    // ---- layer 2: a = Agg(h); out = a @ W2 + b2 ----
    k_self<<<selfGrid, T>>>((const float4*)h_ptr, (float4*)a_ptr, N);
    k_edge<<<edgeGrid, T>>>((const float4*)h_ptr, (float4*)a_ptr, E);
    k_gemm<false><<<gemmGrid, T>>>(a_ptr, W2, b2, out, N);
}

// round 2
// speedup vs baseline: 1.5849x; 1.5849x over previous
#include <cuda_runtime.h>
#include <cuda_bf16.h>
#include <stdint.h>

#define D 128
#define DV 32              // float4 chunks per row
#define MAXN 50048
#define MAXE 1600000

__device__ int   g_row[MAXE];
__device__ int   g_col[MAXE];
__device__ int2  g_adj[MAXE];        // dst-sorted: {src, __float_as_int(dis[src])}
__device__ int   g_deg[MAXN];
__device__ int   g_cnt[MAXN];        // dst in-degree counts, then scatter cursors
__device__ int   g_start[MAXN + 1];  // CSR offsets by dst
__device__ float g_dis[MAXN];
__device__ float g_a[MAXN * D];      // aggregated features
__device__ float g_h[MAXN * D];      // hidden after layer 1
__device__ int   g_is64;

// ---------------------------------------------------------------------------
// Detect edge_index dtype: int64 little-endian values < 2^32 -> every odd
// 32-bit word is zero across 2048 samples.
// ---------------------------------------------------------------------------
__global__ void k_detect(const unsigned* p) {
    __shared__ int any_nz;
    if (threadIdx.x == 0) any_nz = 0;
    __syncthreads();
    int local = 0;
    for (int i = 1 + 2 * threadIdx.x; i < 4096; i += 2 * blockDim.x)
        if (p[i]) local = 1;
    if (local) any_nz = 1;
    __syncthreads();
    if (threadIdx.x == 0) g_is64 = any_nz ? 0 : 1;
}

__global__ void k_init(int N) {
    int i = blockIdx.x * blockDim.x + threadIdx.x;
    if (i < N) { g_deg[i] = 1; g_cnt[i] = 0; }   // deg starts at 1 (self loop)
}

// Parse edges (either dtype), store int32 row/col, count out-degree (by row)
// and in-count (by col) in one pass.
__global__ void k_prep(const void* p, int E) {
    int e = blockIdx.x * blockDim.x + threadIdx.x;
    if (e >= E) return;
    int r, c;
    if (g_is64) {
        const long long* q = (const long long*)p;
        r = (int)q[e];
        c = (int)q[(long long)E + e];
    } else {
        const int* q = (const int*)p;
        r = q[e];
        c = q[E + e];
    }
    g_row[e] = r;
    g_col[e] = c;
    atomicAdd(&g_deg[r], 1);
    atomicAdd(&g_cnt[c], 1);
}

__global__ void k_dis(int N) {
    int i = blockIdx.x * blockDim.x + threadIdx.x;
    if (i < N) g_dis[i] = rsqrtf((float)g_deg[i]);
}

// Single-block exclusive scan of g_cnt -> g_start; zero g_cnt for reuse as
// scatter cursors.
__global__ void k_scan(int N, int E) {
    __shared__ int sh[1024];
    const int tid = threadIdx.x;
    const int per = (N + 1023) >> 10;
    const int base = tid * per;
    int s = 0;
    for (int i = 0; i < per; i++) {
        int idx = base + i;
        if (idx < N) s += g_cnt[idx];
    }
    sh[tid] = s;
    __syncthreads();
    for (int off = 1; off < 1024; off <<= 1) {
        int t = (tid >= off) ? sh[tid - off] : 0;
        __syncthreads();
        sh[tid] += t;
        __syncthreads();
    }
    int run = sh[tid] - s;   // exclusive prefix for this thread's range
    for (int i = 0; i < per; i++) {
        int idx = base + i;
        if (idx < N) {
            int c = g_cnt[idx];
            g_start[idx] = run;
            run += c;
            g_cnt[idx] = 0;
        }
    }
    if (tid == 0) g_start[N] = E;
}

// Scatter edges into dst-sorted adjacency with per-edge weight dis[src].
__global__ void k_scatter(int E) {
    int e = blockIdx.x * blockDim.x + threadIdx.x;
    if (e >= E) return;
    int r = g_row[e];
    int c = g_col[e];
    int pos = g_start[c] + atomicAdd(&g_cnt[c], 1);
    g_adj[pos] = make_int2(r, __float_as_int(g_dis[r]));
}

// ---------------------------------------------------------------------------
// Aggregation: one warp per dst node. dst = dis[n]*(sum_e dis[src]*x[src])
//              + dis[n]^2 * x[n].  Register accumulation, no atomics.
// ---------------------------------------------------------------------------
__global__ void k_agg(const float4* __restrict__ src, float4* __restrict__ dst, int N) {
    int w = (blockIdx.x * blockDim.x + threadIdx.x) >> 5;
    if (w >= N) return;
    const int lane = threadIdx.x & 31;
    int i = g_start[w];
    const int end = g_start[w + 1];

    float4 a0 = make_float4(0.f, 0.f, 0.f, 0.f);
    float4 a1 = make_float4(0.f, 0.f, 0.f, 0.f);
    for (; i + 2 <= end; i += 2) {
        int2 e0 = g_adj[i];
        int2 e1 = g_adj[i + 1];
        float4 v0 = src[e0.x * DV + lane];
        float4 v1 = src[e1.x * DV + lane];
        float w0 = __int_as_float(e0.y);
        float w1 = __int_as_float(e1.y);
        a0.x += w0 * v0.x; a0.y += w0 * v0.y; a0.z += w0 * v0.z; a0.w += w0 * v0.w;
        a1.x += w1 * v1.x; a1.y += w1 * v1.y; a1.z += w1 * v1.z; a1.w += w1 * v1.w;
    }
    if (i < end) {
        int2 e0 = g_adj[i];
        float4 v0 = src[e0.x * DV + lane];
        float w0 = __int_as_float(e0.y);
        a0.x += w0 * v0.x; a0.y += w0 * v0.y; a0.z += w0 * v0.z; a0.w += w0 * v0.w;
    }

    float di = g_dis[w];
    float sw = di * di;
    float4 sv = src[w * DV + lane];
    float4 o;
    o.x = di * (a0.x + a1.x) + sw * sv.x;
    o.y = di * (a0.y + a1.y) + sw * sv.y;
    o.z = di * (a0.z + a1.z) + sw * sv.z;
    o.w = di * (a0.w + a1.w) + sw * sv.w;
    dst[w * DV + lane] = o;
}

// ---------------------------------------------------------------------------
// GEMM: C[N,128] = A[N,128] @ W[128,128] + bias, optional ReLU.
// BM=128, BN=128, BK=32, 256 threads, 8x8 register tile.
// As padded to stride 129 -> conflict-free transposed writes.
// ---------------------------------------------------------------------------
template <bool RELU>
__global__ void k_gemm(const float* __restrict__ A, const float* __restrict__ W,
                       const float* __restrict__ bias, float* __restrict__ C, int N) {
    __shared__ float As[32][129];   // [k][m]
    __shared__ float Ws[32][128];   // [k][n]

    const int tid = threadIdx.x;
    const int tm = tid >> 4;    // 0..15 -> 8 rows each
    const int tn = tid & 15;    // 0..15 -> 8 cols each
    const int row0 = blockIdx.x * 128;

    float acc[8][8];
    #pragma unroll
    for (int i = 0; i < 8; i++)
        #pragma unroll
        for (int j = 0; j < 8; j++) acc[i][j] = 0.f;

    for (int kk = 0; kk < D; kk += 32) {
        // A tile: 128 rows x 32 k = 1024 float4 loads, 4 per thread, k-major store.
        #pragma unroll
        for (int it = 0; it < 4; it++) {
            int idx = tid + it * 256;
            int m  = idx >> 3;       // row in tile (0..127)
            int k4 = idx & 7;        // float4 index along k (0..7)
            float4 v = make_float4(0.f, 0.f, 0.f, 0.f);
            int gr = row0 + m;
            if (gr < N) v = *(const float4*)(A + (long)gr * D + kk + k4 * 4);
            As[k4 * 4 + 0][m] = v.x;
            As[k4 * 4 + 1][m] = v.y;
            As[k4 * 4 + 2][m] = v.z;
            As[k4 * 4 + 3][m] = v.w;
        }
        // W tile: 32 k x 128 n = 1024 float4 loads, 4 per thread.
        #pragma unroll
        for (int it = 0; it < 4; it++) {
            int idx = tid + it * 256;
            int k  = idx >> 5;
            int n4 = idx & 31;
            *(float4*)&Ws[k][n4 * 4] = *(const float4*)(W + (kk + k) * D + n4 * 4);
        }
        __syncthreads();

        #pragma unroll 8
        for (int k = 0; k < 32; k++) {
            float a[8], b[8];
            #pragma unroll
            for (int j = 0; j < 8; j++) a[j] = As[k][tm * 8 + j];
            float4 b0 = *(const float4*)&Ws[k][tn * 8];
            float4 b1 = *(const float4*)&Ws[k][tn * 8 + 4];
            b[0] = b0.x; b[1] = b0.y; b[2] = b0.z; b[3] = b0.w;
            b[4] = b1.x; b[5] = b1.y; b[6] = b1.z; b[7] = b1.w;
            #pragma unroll
            for (int i = 0; i < 8; i++)
                #pragma unroll
                for (int j = 0; j < 8; j++)
                    acc[i][j] += a[i] * b[j];
        }
        __syncthreads();
    }

    float4 bv0 = *(const float4*)(bias + tn * 8);
    float4 bv1 = *(const float4*)(bias + tn * 8 + 4);
    #pragma unroll
    for (int i = 0; i < 8; i++) {
        int gr = row0 + tm * 8 + i;
        if (gr >= N) continue;
        float o[8];
        o[0] = acc[i][0] + bv0.x; o[1] = acc[i][1] + bv0.y;
        o[2] = acc[i][2] + bv0.z; o[3] = acc[i][3] + bv0.w;
        o[4] = acc[i][4] + bv1.x; o[5] = acc[i][5] + bv1.y;
        o[6] = acc[i][6] + bv1.z; o[7] = acc[i][7] + bv1.w;
        if (RELU) {
            #pragma unroll
            for (int j = 0; j < 8; j++) o[j] = fmaxf(o[j], 0.f);
        }
        *(float4*)(C + (long)gr * D + tn * 8)     = make_float4(o[0], o[1], o[2], o[3]);
        *(float4*)(C + (long)gr * D + tn * 8 + 4) = make_float4(o[4], o[5], o[6], o[7]);
    }
}

extern "C" void kernel_launch(void* const* d_in, const int* in_sizes, int n_in,
                              void* d_out, int out_size) {
    const float* x  = (const float*)d_in[0];
    const void*  ei = d_in[1];
    const float* W1 = (const float*)d_in[2];
    const float* b1 = (const float*)d_in[3];
    const float* W2 = (const float*)d_in[4];
    const float* b2 = (const float*)d_in[5];
    float* out = (float*)d_out;

    const int N = in_sizes[0] / D;
    const int E = in_sizes[1] / 2;

    float* a_ptr = nullptr;
    float* h_ptr = nullptr;
    cudaGetSymbolAddress((void**)&a_ptr, g_a);
    cudaGetSymbolAddress((void**)&h_ptr, g_h);

    const int T = 256;
    const int nGrid = (N + T - 1) / T;
    const int eGrid = (E + T - 1) / T;

    // ---- prep: dtype detect, parse+counts, norms, CSR build ----
    k_detect<<<1, 256>>>((const unsigned*)ei);
    k_init<<<nGrid, T>>>(N);
    k_prep<<<eGrid, T>>>(ei, E);
    k_dis<<<nGrid, T>>>(N);
    k_scan<<<1, 1024>>>(N, E);
    k_scatter<<<eGrid, T>>>(E);

    const int aggGrid  = (N * 32 + T - 1) / T;
    const int gemmGrid = (N + 127) / 128;

    // ---- layer 1: a = Agg(x); h = relu(a @ W1 + b1) ----
    k_agg<<<aggGrid, T>>>((const float4*)x, (float4*)a_ptr, N);
    k_gemm<true><<<gemmGrid, T>>>(a_ptr, W1, b1, h_ptr, N);

    // ---- layer 2: a = Agg(h); out = a @ W2 + b2 ----
    k_agg<<<aggGrid, T>>>((const float4*)h_ptr, (float4*)a_ptr, N);
    k_gemm<false><<<gemmGrid, T>>>(a_ptr, W2, b2, out, N);
}